// round 9
// baseline (speedup 1.0000x reference)
#include <cuda_runtime.h>
#include <cstdint>

#define TT 2048
#define BB 64
#define II 256
#define HH 512
#define KK 768            // H + I, hx = [h, x]
#define NCTA 128
#define NTHR 256
#define CHUNK_BYTES 32768 // 128 k-rows x 64 batch x 4B
#define CH (128 * 64)     // floats per chunk

// Scratch (device globals: allocation APIs are forbidden)
__device__ float g_xT[TT][II][BB];      // x transposed: [t][i][b]
__device__ float g_hT[2][HH][BB];       // hidden state, double buffered, [k][b]
__device__ unsigned g_flags[NCTA][32];  // per-CTA arrival flag, 128B stride

// smem floats: 32 mbar pad + Wsd 24576 + bufs 24576 + pres 8192 + cs 256 + bs 16
static const int SMEM_FLOATS = 32 + KK * 32 + 3 * CH + 8 * 16 * 64 + 4 * 64 + 16;
static const int SMEM_BYTES = SMEM_FLOATS * 4;   // 230,592 B (<= 232,448 cap)

// ---------------- helpers ----------------
__device__ __forceinline__ void fma2(unsigned long long& d, unsigned long long a,
                                     unsigned long long b) {
    asm volatile("fma.rn.f32x2 %0, %1, %2, %0;" : "+l"(d) : "l"(a), "l"(b));
}

__device__ __forceinline__ unsigned smem_u32(const void* p) {
    return (unsigned)__cvta_generic_to_shared(p);
}

// One-shot 32KB bulk copy global->smem with mbarrier completion (issued by tid 0)
__device__ __forceinline__ void bulk_ld(float* dst_sm, const float* src, unsigned mbar) {
    unsigned d = smem_u32(dst_sm);
    asm volatile("mbarrier.arrive.expect_tx.shared.b64 _, [%0], %1;"
                 :: "r"(mbar), "r"((unsigned)CHUNK_BYTES) : "memory");
    asm volatile("cp.async.bulk.shared::cluster.global.mbarrier::complete_tx::bytes "
                 "[%0], [%1], %2, [%3];"
                 :: "r"(d), "l"(src), "r"((unsigned)CHUNK_BYTES), "r"(mbar) : "memory");
}

__device__ __forceinline__ void mbar_wait(unsigned mbar, unsigned parity) {
    asm volatile(
        "{\n\t"
        ".reg .pred P1;\n\t"
        "WAIT_LOOP_%=:\n\t"
        "mbarrier.try_wait.parity.acquire.cta.shared::cta.b64 P1, [%0], %1, 0x989680;\n\t"
        "@P1 bra.uni WAIT_DONE_%=;\n\t"
        "bra.uni WAIT_LOOP_%=;\n\t"
        "WAIT_DONE_%=:\n\t"
        "}"
        :: "r"(mbar), "r"(parity) : "memory");
}

// warp0 polls the 32 flags of producer-group `grp` for value >= need
__device__ __forceinline__ void poll_group(int tid, int grp, unsigned need) {
    if (tid < 32) {
        const unsigned* fp = &g_flags[grp * 32 + tid][0];
        unsigned v;
        bool ok;
        do {
            asm volatile("ld.acquire.gpu.global.u32 %0, [%1];"
                         : "=r"(v) : "l"(fp) : "memory");
            ok = (v >= need);
        } while (!__all_sync(0xffffffffu, ok));
    }
}

__device__ __forceinline__ float fast_sigmoid(float z) {
    return __fdividef(1.0f, 1.0f + __expf(-z));
}
__device__ __forceinline__ float fast_tanh(float z) {
    return __fdividef(2.0f, 1.0f + __expf(-2.0f * z)) - 1.0f;
}

// ---------------- x transpose + state reset (merged so the launch stream is
// (xT, lstm)* and ncu -s 5 lands on lstm_persist) ----------------
__global__ void xT_kernel(const float* __restrict__ x) {
    __shared__ float tile[64][65];
    int t = blockIdx.x;

    // reset: blocks 0..63 zero g_hT (both buffers), block 64 zeroes flags
    if (t < 64) {
        for (int i = threadIdx.x; i < 1024; i += blockDim.x)
            (&g_hT[0][0][0])[t * 1024 + i] = 0.0f;
    } else if (t == 64) {
        for (int i = threadIdx.x; i < NCTA * 32; i += blockDim.x)
            (&g_flags[0][0])[i] = 0u;
    }

    for (int ic = 0; ic < 4; ++ic) {
        __syncthreads();
        for (int idx = threadIdx.x; idx < 4096; idx += blockDim.x) {
            int b = idx >> 6, i2 = idx & 63;
            tile[b][i2] = x[((size_t)t * BB + b) * II + ic * 64 + i2];
        }
        __syncthreads();
        for (int idx = threadIdx.x; idx < 4096; idx += blockDim.x) {
            int i2 = idx >> 6, b = idx & 63;
            g_xT[t][ic * 64 + i2][b] = tile[b][i2];
        }
    }
}

// chunk compute: warp q8 handles kl = q8*16 + i within chunk CIDX.
// Thread tile: 4 rows (4rg..4rg+3) x 8 batches (8bg..8bg+7), 16 f32x2 accums.
#define COMPUTE(BUF, CIDX) do {                                               \
    const float* hb = (BUF) + q8 * 16 * 64 + 8 * bg;                          \
    const float* wb = Wsd + ((CIDX) * 128 + q8 * 16) * 32 + 8 * rg;           \
    _Pragma("unroll 4")                                                       \
    for (int i = 0; i < 16; ++i) {                                            \
        ulonglong2 wA = *(const ulonglong2*)(wb + i * 32);      /* rows 4rg,4rg+1 dup */ \
        ulonglong2 wB = *(const ulonglong2*)(wb + i * 32 + 4);  /* rows 4rg+2,4rg+3 dup */ \
        ulonglong2 v0 = *(const ulonglong2*)(hb + i * 64);      /* batches 8bg..8bg+3 */ \
        ulonglong2 v1 = *(const ulonglong2*)(hb + i * 64 + 4);  /* batches 8bg+4..8bg+7 */ \
        fma2(a00, wA.x, v0.x); fma2(a01, wA.x, v0.y); fma2(a02, wA.x, v1.x); fma2(a03, wA.x, v1.y); \
        fma2(a10, wA.y, v0.x); fma2(a11, wA.y, v0.y); fma2(a12, wA.y, v1.x); fma2(a13, wA.y, v1.y); \
        fma2(a20, wB.x, v0.x); fma2(a21, wB.x, v0.y); fma2(a22, wB.x, v1.x); fma2(a23, wB.x, v1.y); \
        fma2(a30, wB.y, v0.x); fma2(a31, wB.y, v0.y); fma2(a32, wB.y, v1.x); fma2(a33, wB.y, v1.y); \
    }                                                                         \
} while (0)

// ---------------- persistent LSTM ----------------
__global__ void __launch_bounds__(NTHR, 1) lstm_persist(
    const float* __restrict__ Wf, const float* __restrict__ bf,
    const float* __restrict__ Wi, const float* __restrict__ bi,
    const float* __restrict__ Wc, const float* __restrict__ bc,
    const float* __restrict__ Wo, const float* __restrict__ bo,
    float* __restrict__ out)
{
    extern __shared__ float sm[];
    float* mbar_f = sm;                   // 3 mbarriers (8B each) in first 128B
    float* Wsd  = sm + 32;                // [KK][32]  rows duplicated-packed for f32x2
    float* bufs = Wsd + KK * 32;          // [3][128][64] chunk ring
    float* pres = bufs + 3 * CH;          // [8][16][64] partial pre-activations (per k-16th)
    float* cs   = pres + 8 * 16 * 64;     // [4][64] cell state (this CTA's 4 hid units)
    float* bs   = cs + 4 * 64;            // [16] biases

    const unsigned mb0 = smem_u32(mbar_f);
    const unsigned mb[3] = { mb0, mb0 + 8, mb0 + 16 };

    const int tid  = threadIdx.x;
    const int cta  = blockIdx.x;
    const int hid0 = cta * 4;             // 4 hidden units per CTA
    const int q8   = tid >> 5;            // warp id = k-sixteenth 0..7 (16 kl of each chunk)
    const int lane = tid & 31;
    const int rg   = lane >> 3;           // 0..3 : rows 4rg .. 4rg+3
    const int bg   = lane & 7;            // 0..7 : batches 8bg .. 8bg+7

    // Load weights for this CTA's 16 gate rows: row r = g*4 + j  (g: f,i,c,o)
    // Duplicated-packed: Wsd[k*32 + 2r] = Wsd[k*32 + 2r + 1] = W[r][k]
    for (int idx = tid; idx < KK * 16; idx += NTHR) {
        int k = idx >> 4, r = idx & 15;
        int g = r >> 2, j = r & 3;
        const float* W = (g == 0) ? Wf : (g == 1) ? Wi : (g == 2) ? Wc : Wo;
        float wv = W[(size_t)(hid0 + j) * KK + k];
        Wsd[k * 32 + 2 * r]     = wv;
        Wsd[k * 32 + 2 * r + 1] = wv;
    }
    if (tid < 16) {
        int g = tid >> 2, j = tid & 3;
        const float* Bv = (g == 0) ? bf : (g == 1) ? bi : (g == 2) ? bc : bo;
        bs[tid] = Bv[hid0 + j];
    }
    for (int idx = tid; idx < 4 * 64; idx += NTHR) cs[idx] = 0.0f;
    if (tid == 0) {
        #pragma unroll
        for (int j = 0; j < 3; ++j)
            asm volatile("mbarrier.init.shared.b64 [%0], 1;" :: "r"(mb[j]) : "memory");
    }
    __syncthreads();

    // prologue: x0(0)->s0, x1(0)->s1, h0(0)->s2 (h(0)=0, zeroed by xT_kernel)
    if (tid == 0) {
        asm volatile("fence.proxy.async;" ::: "memory");
        bulk_ld(bufs + 0 * CH, &g_xT[0][0][0],        mb[0]);
        bulk_ld(bufs + 1 * CH, &g_xT[0][0][0] + 8192, mb[1]);
        bulk_ld(bufs + 2 * CH, &g_hT[0][0][0],        mb[2]);
    }

    for (int t = 0; t < TT; ++t) {
        const float* hsrc = &g_hT[t & 1][0][0];

        unsigned long long a00 = 0, a01 = 0, a02 = 0, a03 = 0,
                           a10 = 0, a11 = 0, a12 = 0, a13 = 0,
                           a20 = 0, a21 = 0, a22 = 0, a23 = 0,
                           a30 = 0, a31 = 0, a32 = 0, a33 = 0;

        // ---- x0 (s0 @0): weights chunk 4; warp0 first secures group1 ----
        poll_group(tid, 1, (unsigned)t);
        mbar_wait(mb[0], 0);
        COMPUTE(bufs + 0 * CH, 4);
        __syncthreads();                               // s0 free
        if (tid == 0) bulk_ld(bufs + 0 * CH, hsrc + 8192, mb[0]);     // h1 -> s0

        // ---- h0 (s2 @0): weights chunk 0; warp0 secures group2 ----
        poll_group(tid, 2, (unsigned)t);
        mbar_wait(mb[2], 0);
        COMPUTE(bufs + 2 * CH, 0);
        __syncthreads();                               // s2 free
        if (tid == 0) bulk_ld(bufs + 2 * CH, hsrc + 16384, mb[2]);    // h2 -> s2

        // ---- x1 (s1 @0): weights chunk 5; warp0 secures group3 ----
        poll_group(tid, 3, (unsigned)t);
        mbar_wait(mb[1], 0);
        COMPUTE(bufs + 1 * CH, 5);
        __syncthreads();                               // s1 free
        if (tid == 0) bulk_ld(bufs + 1 * CH, hsrc + 24576, mb[1]);    // h3 -> s1

        // ---- h1 (s0 @1), h2 (s2 @1), h3 (s1 @1) ----
        mbar_wait(mb[0], 1);
        COMPUTE(bufs + 0 * CH, 1);
        mbar_wait(mb[2], 1);
        COMPUTE(bufs + 2 * CH, 2);
        mbar_wait(mb[1], 1);
        COMPUTE(bufs + 1 * CH, 3);

        // dump partial pre-activations: pres[q8][row][b]
        {
            float* pp = pres + (q8 * 16 + 4 * rg) * 64 + 8 * bg;
            ulonglong2 s;
            s.x = a00; s.y = a01; *(ulonglong2*)(pp + 0 * 64)     = s;
            s.x = a02; s.y = a03; *(ulonglong2*)(pp + 0 * 64 + 4) = s;
            s.x = a10; s.y = a11; *(ulonglong2*)(pp + 1 * 64)     = s;
            s.x = a12; s.y = a13; *(ulonglong2*)(pp + 1 * 64 + 4) = s;
            s.x = a20; s.y = a21; *(ulonglong2*)(pp + 2 * 64)     = s;
            s.x = a22; s.y = a23; *(ulonglong2*)(pp + 2 * 64 + 4) = s;
            s.x = a30; s.y = a31; *(ulonglong2*)(pp + 3 * 64)     = s;
            s.x = a32; s.y = a33; *(ulonglong2*)(pp + 3 * 64 + 4) = s;
        }
        __syncthreads();    // pres complete; all slots consumed

        // prefetch next step's x chunks (runs under gates + publish)
        if (tid == 0 && t + 1 < TT) {
            const float* xn = &g_xT[t + 1][0][0];
            bulk_ld(bufs + 0 * CH, xn,        mb[0]);
            bulk_ld(bufs + 1 * CH, xn + 8192, mb[1]);
        }

        // gates + state update: 256 cells, one per thread (coalesced h-store)
        float* hdst = &g_hT[(t + 1) & 1][0][0];
        const int j = tid >> 6, b = tid & 63;
        float hn, cn;
        {
            float zf = bs[j],      zi = bs[4 + j],
                  zc = bs[8 + j],  zo = bs[12 + j];
            #pragma unroll
            for (int qq = 0; qq < 8; ++qq) {
                zf += pres[(qq * 16 + 0  + j) * 64 + b];
                zi += pres[(qq * 16 + 4  + j) * 64 + b];
                zc += pres[(qq * 16 + 8  + j) * 64 + b];
                zo += pres[(qq * 16 + 12 + j) * 64 + b];
            }
            float fg = fast_sigmoid(zf);
            float ig = fast_sigmoid(zi);
            float og = fast_sigmoid(zo);
            cn = fg * cs[j * 64 + b] + ig * fast_tanh(zc);
            hn = og * fast_tanh(cn);
            cs[j * 64 + b] = cn;
            hdst[(hid0 + j) * BB + b] = hn;
        }

        // publish this CTA's arrival (h(t+1) slice visible) BEFORE out stores
        __threadfence();
        __syncthreads();
        if (tid == 0) {
            asm volatile("st.release.gpu.global.u32 [%0], %1;"
                         :: "l"(&g_flags[cta][0]), "r"((unsigned)(t + 1))
                         : "memory");
        }

        // cross-boundary prefetch of h0(t+1): poll group0 then TMA into s2
        if (t + 1 < TT) {
            poll_group(tid, 0, (unsigned)(t + 1));
            if (tid == 0) bulk_ld(bufs + 2 * CH, &g_hT[(t + 1) & 1][0][0], mb[2]);
        }

        // out stores (not on the inter-CTA critical path)
        out[((size_t)t * BB + b) * HH + hid0 + j] = hn;
        if (t == TT - 1) {
            out[(size_t)TT * BB * HH + (size_t)b * HH + hid0 + j] = hn;                    // h_last
            out[(size_t)TT * BB * HH + (size_t)BB * HH + (size_t)b * HH + hid0 + j] = cn;  // c_last
        }
    }
}

// ---------------- launch ----------------
extern "C" void kernel_launch(void* const* d_in, const int* in_sizes, int n_in,
                              void* d_out, int out_size) {
    const float* x  = (const float*)d_in[0];
    const float* Wf = (const float*)d_in[1];
    const float* bf = (const float*)d_in[2];
    const float* Wi = (const float*)d_in[3];
    const float* bi = (const float*)d_in[4];
    const float* Wc = (const float*)d_in[5];
    const float* bc = (const float*)d_in[6];
    const float* Wo = (const float*)d_in[7];
    const float* bo = (const float*)d_in[8];
    float* out = (float*)d_out;

    cudaFuncSetAttribute(lstm_persist,
                         cudaFuncAttributeMaxDynamicSharedMemorySize, SMEM_BYTES);

    xT_kernel<<<TT, 256>>>(x);
    lstm_persist<<<NCTA, NTHR, SMEM_BYTES>>>(Wf, bf, Wi, bi, Wc, bc, Wo, bo, out);
}

// round 10
// speedup vs baseline: 1.0228x; 1.0228x over previous
#include <cuda_runtime.h>
#include <cstdint>

#define TT 2048
#define BB 64
#define II 256
#define HH 512
#define KK 768            // H + I, hx = [h, x]
#define NCTA 128
#define NTHR 256
#define CHUNK_BYTES 32768 // 128 k-rows x 64 batch x 4B
#define CH (128 * 64)     // floats per chunk

// Scratch (device globals: allocation APIs are forbidden)
__device__ float g_xT[TT][II][BB];      // x transposed: [t][i][b]
__device__ float g_hT[2][HH][BB];       // hidden state, double buffered, [k][b]
__device__ unsigned g_flags[NCTA][32];  // per-CTA arrival flag, 128B stride

// smem floats: 32 mbar pad + Wsd 24576 + bufs 24576 + pres 8192 + cs 256 + bs 16
static const int SMEM_FLOATS = 32 + KK * 32 + 3 * CH + 8 * 16 * 64 + 4 * 64 + 16;
static const int SMEM_BYTES = SMEM_FLOATS * 4;   // 230,592 B (<= 232,448 cap)

// ---------------- helpers ----------------
__device__ __forceinline__ void fma2(unsigned long long& d, unsigned long long a,
                                     unsigned long long b) {
    asm volatile("fma.rn.f32x2 %0, %1, %2, %0;" : "+l"(d) : "l"(a), "l"(b));
}

__device__ __forceinline__ unsigned smem_u32(const void* p) {
    return (unsigned)__cvta_generic_to_shared(p);
}

// One-shot 32KB bulk copy global->smem with mbarrier completion (issued by tid 0)
__device__ __forceinline__ void bulk_ld(float* dst_sm, const float* src, unsigned mbar) {
    unsigned d = smem_u32(dst_sm);
    asm volatile("mbarrier.arrive.expect_tx.shared.b64 _, [%0], %1;"
                 :: "r"(mbar), "r"((unsigned)CHUNK_BYTES) : "memory");
    asm volatile("cp.async.bulk.shared::cluster.global.mbarrier::complete_tx::bytes "
                 "[%0], [%1], %2, [%3];"
                 :: "r"(d), "l"(src), "r"((unsigned)CHUNK_BYTES), "r"(mbar) : "memory");
}

__device__ __forceinline__ void mbar_wait(unsigned mbar, unsigned parity) {
    asm volatile(
        "{\n\t"
        ".reg .pred P1;\n\t"
        "WAIT_LOOP_%=:\n\t"
        "mbarrier.try_wait.parity.acquire.cta.shared::cta.b64 P1, [%0], %1, 0x989680;\n\t"
        "@P1 bra.uni WAIT_DONE_%=;\n\t"
        "bra.uni WAIT_LOOP_%=;\n\t"
        "WAIT_DONE_%=:\n\t"
        "}"
        :: "r"(mbar), "r"(parity) : "memory");
}

// warp0 polls the 32 flags of producer-group `grp` for value >= need
__device__ __forceinline__ void poll_group(int tid, int grp, unsigned need) {
    if (tid < 32) {
        const unsigned* fp = &g_flags[grp * 32 + tid][0];
        unsigned v;
        bool ok;
        do {
            asm volatile("ld.acquire.gpu.global.u32 %0, [%1];"
                         : "=r"(v) : "l"(fp) : "memory");
            ok = (v >= need);
        } while (!__all_sync(0xffffffffu, ok));
    }
}

__device__ __forceinline__ float fast_sigmoid(float z) {
    return __fdividef(1.0f, 1.0f + __expf(-z));
}
__device__ __forceinline__ float fast_tanh(float z) {
    return __fdividef(2.0f, 1.0f + __expf(-2.0f * z)) - 1.0f;
}

// ---------------- x transpose + state reset (merged so the launch stream is
// (xT, lstm)* and ncu -s 5 lands on lstm_persist) ----------------
__global__ void xT_kernel(const float* __restrict__ x) {
    __shared__ float tile[64][65];
    int t = blockIdx.x;

    // reset: blocks 0..63 zero g_hT (both buffers), block 64 zeroes flags
    if (t < 64) {
        for (int i = threadIdx.x; i < 1024; i += blockDim.x)
            (&g_hT[0][0][0])[t * 1024 + i] = 0.0f;
    } else if (t == 64) {
        for (int i = threadIdx.x; i < NCTA * 32; i += blockDim.x)
            (&g_flags[0][0])[i] = 0u;
    }

    for (int ic = 0; ic < 4; ++ic) {
        __syncthreads();
        for (int idx = threadIdx.x; idx < 4096; idx += blockDim.x) {
            int b = idx >> 6, i2 = idx & 63;
            tile[b][i2] = x[((size_t)t * BB + b) * II + ic * 64 + i2];
        }
        __syncthreads();
        for (int idx = threadIdx.x; idx < 4096; idx += blockDim.x) {
            int i2 = idx >> 6, b = idx & 63;
            g_xT[t][ic * 64 + i2][b] = tile[b][i2];
        }
    }
}

// chunk compute: warp q8 handles kl = q8*16 + i within chunk CIDX.
// Thread tile: 4 rows (4rg..4rg+3) x 8 batches (8bg..8bg+7), 16 f32x2 accums.
#define COMPUTE(BUF, CIDX) do {                                               \
    const float* hb = (BUF) + q8 * 16 * 64 + 8 * bg;                          \
    const float* wb = Wsd + ((CIDX) * 128 + q8 * 16) * 32 + 8 * rg;           \
    _Pragma("unroll 4")                                                       \
    for (int i = 0; i < 16; ++i) {                                            \
        ulonglong2 wA = *(const ulonglong2*)(wb + i * 32);      /* rows 4rg,4rg+1 dup */ \
        ulonglong2 wB = *(const ulonglong2*)(wb + i * 32 + 4);  /* rows 4rg+2,4rg+3 dup */ \
        ulonglong2 v0 = *(const ulonglong2*)(hb + i * 64);      /* batches 8bg..8bg+3 */ \
        ulonglong2 v1 = *(const ulonglong2*)(hb + i * 64 + 4);  /* batches 8bg+4..8bg+7 */ \
        fma2(a00, wA.x, v0.x); fma2(a01, wA.x, v0.y); fma2(a02, wA.x, v1.x); fma2(a03, wA.x, v1.y); \
        fma2(a10, wA.y, v0.x); fma2(a11, wA.y, v0.y); fma2(a12, wA.y, v1.x); fma2(a13, wA.y, v1.y); \
        fma2(a20, wB.x, v0.x); fma2(a21, wB.x, v0.y); fma2(a22, wB.x, v1.x); fma2(a23, wB.x, v1.y); \
        fma2(a30, wB.y, v0.x); fma2(a31, wB.y, v0.y); fma2(a32, wB.y, v1.x); fma2(a33, wB.y, v1.y); \
    }                                                                         \
} while (0)

// ---------------- persistent LSTM ----------------
__global__ void __launch_bounds__(NTHR, 1) lstm_persist(
    const float* __restrict__ Wf, const float* __restrict__ bf,
    const float* __restrict__ Wi, const float* __restrict__ bi,
    const float* __restrict__ Wc, const float* __restrict__ bc,
    const float* __restrict__ Wo, const float* __restrict__ bo,
    float* __restrict__ out)
{
    extern __shared__ float sm[];
    float* mbar_f = sm;                   // 3 mbarriers (8B each) in first 128B
    float* Wsd  = sm + 32;                // [KK][32]  rows duplicated-packed for f32x2
    float* bufs = Wsd + KK * 32;          // [3][128][64] chunk ring
    float* pres = bufs + 3 * CH;          // [8][16][64] partial pre-activations (per k-16th)
    float* cs   = pres + 8 * 16 * 64;     // [4][64] cell state (this CTA's 4 hid units)
    float* bs   = cs + 4 * 64;            // [16] biases

    const unsigned mb0 = smem_u32(mbar_f);
    const unsigned mb[3] = { mb0, mb0 + 8, mb0 + 16 };

    const int tid  = threadIdx.x;
    const int cta  = blockIdx.x;
    const int hid0 = cta * 4;             // 4 hidden units per CTA
    const int q8   = tid >> 5;            // warp id = k-sixteenth 0..7 (16 kl of each chunk)
    const int lane = tid & 31;
    const int rg   = lane >> 3;           // 0..3 : rows 4rg .. 4rg+3
    const int bg   = lane & 7;            // 0..7 : batches 8bg .. 8bg+7

    // Load weights for this CTA's 16 gate rows: row r = g*4 + j  (g: f,i,c,o)
    // Duplicated-packed: Wsd[k*32 + 2r] = Wsd[k*32 + 2r + 1] = W[r][k]
    for (int idx = tid; idx < KK * 16; idx += NTHR) {
        int k = idx >> 4, r = idx & 15;
        int g = r >> 2, j = r & 3;
        const float* W = (g == 0) ? Wf : (g == 1) ? Wi : (g == 2) ? Wc : Wo;
        float wv = W[(size_t)(hid0 + j) * KK + k];
        Wsd[k * 32 + 2 * r]     = wv;
        Wsd[k * 32 + 2 * r + 1] = wv;
    }
    if (tid < 16) {
        int g = tid >> 2, j = tid & 3;
        const float* Bv = (g == 0) ? bf : (g == 1) ? bi : (g == 2) ? bc : bo;
        bs[tid] = Bv[hid0 + j];
    }
    for (int idx = tid; idx < 4 * 64; idx += NTHR) cs[idx] = 0.0f;
    if (tid == 0) {
        #pragma unroll
        for (int j = 0; j < 3; ++j)
            asm volatile("mbarrier.init.shared.b64 [%0], 1;" :: "r"(mb[j]) : "memory");
    }
    __syncthreads();

    // prologue: x0(0)->s0, x1(0)->s1, h0(0)->s2 (h(0)=0, zeroed by xT_kernel)
    if (tid == 0) {
        asm volatile("fence.proxy.async;" ::: "memory");
        bulk_ld(bufs + 0 * CH, &g_xT[0][0][0],        mb[0]);
        bulk_ld(bufs + 1 * CH, &g_xT[0][0][0] + 8192, mb[1]);
        bulk_ld(bufs + 2 * CH, &g_hT[0][0][0],        mb[2]);
    }

    for (int t = 0; t < TT; ++t) {
        const float* hsrc = &g_hT[t & 1][0][0];

        unsigned long long a00 = 0, a01 = 0, a02 = 0, a03 = 0,
                           a10 = 0, a11 = 0, a12 = 0, a13 = 0,
                           a20 = 0, a21 = 0, a22 = 0, a23 = 0,
                           a30 = 0, a31 = 0, a32 = 0, a33 = 0;

        // ---- x0 (s0 @0): weights chunk 4; warp0 first secures group1 ----
        poll_group(tid, 1, (unsigned)t);
        mbar_wait(mb[0], 0);
        COMPUTE(bufs + 0 * CH, 4);
        __syncthreads();                               // s0 free
        if (tid == 0) bulk_ld(bufs + 0 * CH, hsrc + 8192, mb[0]);     // h1 -> s0

        // ---- h0 (s2 @0): weights chunk 0; warp0 secures group2 ----
        poll_group(tid, 2, (unsigned)t);
        mbar_wait(mb[2], 0);
        COMPUTE(bufs + 2 * CH, 0);
        __syncthreads();                               // s2 free
        if (tid == 0) bulk_ld(bufs + 2 * CH, hsrc + 16384, mb[2]);    // h2 -> s2

        // ---- x1 (s1 @0): weights chunk 5; warp0 secures group3 ----
        poll_group(tid, 3, (unsigned)t);
        mbar_wait(mb[1], 0);
        COMPUTE(bufs + 1 * CH, 5);
        __syncthreads();                               // s1 free
        if (tid == 0) bulk_ld(bufs + 1 * CH, hsrc + 24576, mb[1]);    // h3 -> s1

        // ---- h1 (s0 @1), h2 (s2 @1), h3 (s1 @1) ----
        mbar_wait(mb[0], 1);
        COMPUTE(bufs + 0 * CH, 1);
        mbar_wait(mb[2], 1);
        COMPUTE(bufs + 2 * CH, 2);
        mbar_wait(mb[1], 1);
        COMPUTE(bufs + 1 * CH, 3);

        // dump partial pre-activations: pres[q8][row][b]
        {
            float* pp = pres + (q8 * 16 + 4 * rg) * 64 + 8 * bg;
            ulonglong2 s;
            s.x = a00; s.y = a01; *(ulonglong2*)(pp + 0 * 64)     = s;
            s.x = a02; s.y = a03; *(ulonglong2*)(pp + 0 * 64 + 4) = s;
            s.x = a10; s.y = a11; *(ulonglong2*)(pp + 1 * 64)     = s;
            s.x = a12; s.y = a13; *(ulonglong2*)(pp + 1 * 64 + 4) = s;
            s.x = a20; s.y = a21; *(ulonglong2*)(pp + 2 * 64)     = s;
            s.x = a22; s.y = a23; *(ulonglong2*)(pp + 2 * 64 + 4) = s;
            s.x = a30; s.y = a31; *(ulonglong2*)(pp + 3 * 64)     = s;
            s.x = a32; s.y = a33; *(ulonglong2*)(pp + 3 * 64 + 4) = s;
        }
        __syncthreads();    // pres complete; all slots consumed

        // prefetch next step's x chunks (runs under gates + publish)
        if (tid == 0 && t + 1 < TT) {
            const float* xn = &g_xT[t + 1][0][0];
            bulk_ld(bufs + 0 * CH, xn,        mb[0]);
            bulk_ld(bufs + 1 * CH, xn + 8192, mb[1]);
        }

        // gates + state update: 256 cells, one per thread (coalesced h-store)
        float* hdst = &g_hT[(t + 1) & 1][0][0];
        const int j = tid >> 6, b = tid & 63;
        float hn, cn;
        {
            float zf = bs[j],      zi = bs[4 + j],
                  zc = bs[8 + j],  zo = bs[12 + j];
            #pragma unroll
            for (int qq = 0; qq < 8; ++qq) {
                zf += pres[(qq * 16 + 0  + j) * 64 + b];
                zi += pres[(qq * 16 + 4  + j) * 64 + b];
                zc += pres[(qq * 16 + 8  + j) * 64 + b];
                zo += pres[(qq * 16 + 12 + j) * 64 + b];
            }
            float fg = fast_sigmoid(zf);
            float ig = fast_sigmoid(zi);
            float og = fast_sigmoid(zo);
            cn = fg * cs[j * 64 + b] + ig * fast_tanh(zc);
            hn = og * fast_tanh(cn);
            cs[j * 64 + b] = cn;
            hdst[(hid0 + j) * BB + b] = hn;
        }

        // publish this CTA's arrival (h(t+1) slice visible) BEFORE out stores
        __threadfence();
        __syncthreads();
        if (tid == 0) {
            asm volatile("st.release.gpu.global.u32 [%0], %1;"
                         :: "l"(&g_flags[cta][0]), "r"((unsigned)(t + 1))
                         : "memory");
        }

        // cross-boundary prefetch of h0(t+1): poll group0 then TMA into s2
        if (t + 1 < TT) {
            poll_group(tid, 0, (unsigned)(t + 1));
            if (tid == 0) bulk_ld(bufs + 2 * CH, &g_hT[(t + 1) & 1][0][0], mb[2]);
        }

        // out stores (not on the inter-CTA critical path)
        out[((size_t)t * BB + b) * HH + hid0 + j] = hn;
        if (t == TT - 1) {
            out[(size_t)TT * BB * HH + (size_t)b * HH + hid0 + j] = hn;                    // h_last
            out[(size_t)TT * BB * HH + (size_t)BB * HH + (size_t)b * HH + hid0 + j] = cn;  // c_last
        }
    }
}

// ---------------- launch ----------------
extern "C" void kernel_launch(void* const* d_in, const int* in_sizes, int n_in,
                              void* d_out, int out_size) {
    const float* x  = (const float*)d_in[0];
    const float* Wf = (const float*)d_in[1];
    const float* bf = (const float*)d_in[2];
    const float* Wi = (const float*)d_in[3];
    const float* bi = (const float*)d_in[4];
    const float* Wc = (const float*)d_in[5];
    const float* bc = (const float*)d_in[6];
    const float* Wo = (const float*)d_in[7];
    const float* bo = (const float*)d_in[8];
    float* out = (float*)d_out;

    cudaFuncSetAttribute(lstm_persist,
                         cudaFuncAttributeMaxDynamicSharedMemorySize, SMEM_BYTES);

    xT_kernel<<<TT, 256>>>(x);
    lstm_persist<<<NCTA, NTHR, SMEM_BYTES>>>(Wf, bf, Wi, bi, Wc, bc, Wo, bo, out);
}

// round 11
// speedup vs baseline: 1.3307x; 1.3010x over previous
#include <cuda_runtime.h>
#include <cstdint>

#define TT 2048
#define BB 64
#define II 256
#define HH 512
#define KK 768            // H + I, hx = [h, x]
#define NCTA 128
#define NTHR 512
#define CHUNK_BYTES 32768 // 128 k-rows x 64 batch x 4B
#define CH (128 * 64)     // floats per chunk

// Scratch (device globals: allocation APIs are forbidden)
__device__ float g_xT[TT][II][BB];      // x transposed: [t][i][b]
__device__ float g_hT[2][HH][BB];       // hidden state, double buffered, [k][b]
__device__ unsigned g_flags[NCTA][32];  // per-CTA arrival flag, 128B stride

// smem floats: 32 mbar pad + Wsd 24576 + bufs 24576 + pres 8192 + cs 256 + bs 16
static const int SMEM_FLOATS = 32 + KK * 32 + 3 * CH + 8 * 16 * 64 + 4 * 64 + 16;
static const int SMEM_BYTES = SMEM_FLOATS * 4;   // 230,592 B (<= 232,448 cap)

// ---------------- helpers ----------------
__device__ __forceinline__ void fma2(unsigned long long& d, unsigned long long a,
                                     unsigned long long b) {
    asm volatile("fma.rn.f32x2 %0, %1, %2, %0;" : "+l"(d) : "l"(a), "l"(b));
}
__device__ __forceinline__ void add2(unsigned long long& d, unsigned long long a) {
    asm volatile("add.rn.f32x2 %0, %0, %1;" : "+l"(d) : "l"(a));
}

__device__ __forceinline__ unsigned smem_u32(const void* p) {
    return (unsigned)__cvta_generic_to_shared(p);
}

// One-shot 32KB bulk copy global->smem with mbarrier completion (issued by tid 0)
__device__ __forceinline__ void bulk_ld(float* dst_sm, const float* src, unsigned mbar) {
    unsigned d = smem_u32(dst_sm);
    asm volatile("mbarrier.arrive.expect_tx.shared.b64 _, [%0], %1;"
                 :: "r"(mbar), "r"((unsigned)CHUNK_BYTES) : "memory");
    asm volatile("cp.async.bulk.shared::cluster.global.mbarrier::complete_tx::bytes "
                 "[%0], [%1], %2, [%3];"
                 :: "r"(d), "l"(src), "r"((unsigned)CHUNK_BYTES), "r"(mbar) : "memory");
}

__device__ __forceinline__ void mbar_wait(unsigned mbar, unsigned parity) {
    asm volatile(
        "{\n\t"
        ".reg .pred P1;\n\t"
        "WAIT_LOOP_%=:\n\t"
        "mbarrier.try_wait.parity.acquire.cta.shared::cta.b64 P1, [%0], %1, 0x989680;\n\t"
        "@P1 bra.uni WAIT_DONE_%=;\n\t"
        "bra.uni WAIT_LOOP_%=;\n\t"
        "WAIT_DONE_%=:\n\t"
        "}"
        :: "r"(mbar), "r"(parity) : "memory");
}

// warp0 polls the 32 flags of producer-group `grp` for value >= need
__device__ __forceinline__ void poll_group(int tid, int grp, unsigned need) {
    if (tid < 32) {
        const unsigned* fp = &g_flags[grp * 32 + tid][0];
        unsigned v;
        bool ok;
        do {
            asm volatile("ld.acquire.gpu.global.u32 %0, [%1];"
                         : "=r"(v) : "l"(fp) : "memory");
            ok = (v >= need);
        } while (!__all_sync(0xffffffffu, ok));
    }
}

__device__ __forceinline__ float fast_sigmoid(float z) {
    return __fdividef(1.0f, 1.0f + __expf(-z));
}
__device__ __forceinline__ float fast_tanh(float z) {
    return __fdividef(2.0f, 1.0f + __expf(-2.0f * z)) - 1.0f;
}

// ---------------- x transpose + state reset ----------------
__global__ void xT_kernel(const float* __restrict__ x) {
    __shared__ float tile[64][65];
    int t = blockIdx.x;

    if (t < 64) {
        for (int i = threadIdx.x; i < 1024; i += blockDim.x)
            (&g_hT[0][0][0])[t * 1024 + i] = 0.0f;
    } else if (t == 64) {
        for (int i = threadIdx.x; i < NCTA * 32; i += blockDim.x)
            (&g_flags[0][0])[i] = 0u;
    }

    for (int ic = 0; ic < 4; ++ic) {
        __syncthreads();
        for (int idx = threadIdx.x; idx < 4096; idx += blockDim.x) {
            int b = idx >> 6, i2 = idx & 63;
            tile[b][i2] = x[((size_t)t * BB + b) * II + ic * 64 + i2];
        }
        __syncthreads();
        for (int idx = threadIdx.x; idx < 4096; idx += blockDim.x) {
            int i2 = idx >> 6, b = idx & 63;
            g_xT[t][ic * 64 + i2][b] = tile[b][i2];
        }
    }
}

// chunk compute: warp w16 handles kl = w16*8 + i (i=0..7) within chunk CIDX.
// Thread tile: 4 rows (4rg..4rg+3) x 8 batches {4bg..4bg+3} U {32+4bg..32+4bg+3}.
// Both v loads are conflict-free (16B x 8 lanes contiguous within a 128B half).
#define COMPUTE(BUF, CIDX) do {                                               \
    const float* hb = (BUF) + w16 * 8 * 64 + 4 * bg;                          \
    const float* wb = Wsd + ((CIDX) * 128 + w16 * 8) * 32 + 8 * rg;           \
    _Pragma("unroll")                                                         \
    for (int i = 0; i < 8; ++i) {                                             \
        ulonglong2 wA = *(const ulonglong2*)(wb + i * 32);      /* rows 4rg,4rg+1 dup */ \
        ulonglong2 wB = *(const ulonglong2*)(wb + i * 32 + 4);  /* rows 4rg+2,4rg+3 dup */ \
        ulonglong2 v0 = *(const ulonglong2*)(hb + i * 64);      /* batches 4bg..4bg+3 */ \
        ulonglong2 v1 = *(const ulonglong2*)(hb + i * 64 + 32); /* batches 32+4bg.. */   \
        fma2(a00, wA.x, v0.x); fma2(a01, wA.x, v0.y); fma2(a02, wA.x, v1.x); fma2(a03, wA.x, v1.y); \
        fma2(a10, wA.y, v0.x); fma2(a11, wA.y, v0.y); fma2(a12, wA.y, v1.x); fma2(a13, wA.y, v1.y); \
        fma2(a20, wB.x, v0.x); fma2(a21, wB.x, v0.y); fma2(a22, wB.x, v1.x); fma2(a23, wB.x, v1.y); \
        fma2(a30, wB.y, v0.x); fma2(a31, wB.y, v0.y); fma2(a32, wB.y, v1.x); fma2(a33, wB.y, v1.y); \
    }                                                                         \
} while (0)

// ---------------- persistent LSTM ----------------
__global__ void __launch_bounds__(NTHR, 1) lstm_persist(
    const float* __restrict__ Wf, const float* __restrict__ bf,
    const float* __restrict__ Wi, const float* __restrict__ bi,
    const float* __restrict__ Wc, const float* __restrict__ bc,
    const float* __restrict__ Wo, const float* __restrict__ bo,
    float* __restrict__ out)
{
    extern __shared__ float sm[];
    float* mbar_f = sm;                   // 3 mbarriers (8B each) in first 128B
    float* Wsd  = sm + 32;                // [KK][32]  rows duplicated-packed for f32x2
    float* bufs = Wsd + KK * 32;          // [3][128][64] chunk ring
    float* pres = bufs + 3 * CH;          // [8][16][64] reduced partial pre-activations
    float* cs   = pres + 8 * 16 * 64;     // [4][64] cell state (this CTA's 4 hid units)
    float* bs   = cs + 4 * 64;            // [16] biases

    const unsigned mb0 = smem_u32(mbar_f);
    const unsigned mb[3] = { mb0, mb0 + 8, mb0 + 16 };

    const int tid  = threadIdx.x;
    const int cta  = blockIdx.x;
    const int hid0 = cta * 4;             // 4 hidden units per CTA
    const int w16  = tid >> 5;            // warp id 0..15 = k-eighth-of-chunk
    const int lane = tid & 31;
    const int rg   = lane >> 3;           // 0..3 : rows 4rg .. 4rg+3
    const int bg   = lane & 7;            // 0..7 : batch group

    // Load weights for this CTA's 16 gate rows: row r = g*4 + j  (g: f,i,c,o)
    for (int idx = tid; idx < KK * 16; idx += NTHR) {
        int k = idx >> 4, r = idx & 15;
        int g = r >> 2, j = r & 3;
        const float* W = (g == 0) ? Wf : (g == 1) ? Wi : (g == 2) ? Wc : Wo;
        float wv = W[(size_t)(hid0 + j) * KK + k];
        Wsd[k * 32 + 2 * r]     = wv;
        Wsd[k * 32 + 2 * r + 1] = wv;
    }
    if (tid < 16) {
        int g = tid >> 2, j = tid & 3;
        const float* Bv = (g == 0) ? bf : (g == 1) ? bi : (g == 2) ? bc : bo;
        bs[tid] = Bv[hid0 + j];
    }
    for (int idx = tid; idx < 4 * 64; idx += NTHR) cs[idx] = 0.0f;
    if (tid == 0) {
        #pragma unroll
        for (int j = 0; j < 3; ++j)
            asm volatile("mbarrier.init.shared.b64 [%0], 1;" :: "r"(mb[j]) : "memory");
    }
    __syncthreads();

    // prologue: x0(0)->s0, x1(0)->s1, h0(0)->s2 (h(0)=0, zeroed by xT_kernel)
    if (tid == 0) {
        asm volatile("fence.proxy.async;" ::: "memory");
        bulk_ld(bufs + 0 * CH, &g_xT[0][0][0],        mb[0]);
        bulk_ld(bufs + 1 * CH, &g_xT[0][0][0] + 8192, mb[1]);
        bulk_ld(bufs + 2 * CH, &g_hT[0][0][0],        mb[2]);
    }

    for (int t = 0; t < TT; ++t) {
        const float* hsrc = &g_hT[t & 1][0][0];

        unsigned long long a00 = 0, a01 = 0, a02 = 0, a03 = 0,
                           a10 = 0, a11 = 0, a12 = 0, a13 = 0,
                           a20 = 0, a21 = 0, a22 = 0, a23 = 0,
                           a30 = 0, a31 = 0, a32 = 0, a33 = 0;

        // ---- x0 (s0 @0): weights chunk 4; warp0 first secures group1 ----
        poll_group(tid, 1, (unsigned)t);
        mbar_wait(mb[0], 0);
        COMPUTE(bufs + 0 * CH, 4);
        __syncthreads();                               // s0 free
        if (tid == 0) bulk_ld(bufs + 0 * CH, hsrc + 8192, mb[0]);     // h1 -> s0

        // ---- h0 (s2 @0): weights chunk 0; warp0 secures group2 ----
        poll_group(tid, 2, (unsigned)t);
        mbar_wait(mb[2], 0);
        COMPUTE(bufs + 2 * CH, 0);
        __syncthreads();                               // s2 free
        if (tid == 0) bulk_ld(bufs + 2 * CH, hsrc + 16384, mb[2]);    // h2 -> s2

        // ---- x1 (s1 @0): weights chunk 5; warp0 secures group3 ----
        poll_group(tid, 3, (unsigned)t);
        mbar_wait(mb[1], 0);
        COMPUTE(bufs + 1 * CH, 5);
        __syncthreads();                               // s1 free
        if (tid == 0) bulk_ld(bufs + 1 * CH, hsrc + 24576, mb[1]);    // h3 -> s1

        // ---- h1 (s0 @1), h2 (s2 @1), h3 (s1 @1) ----
        mbar_wait(mb[0], 1);
        COMPUTE(bufs + 0 * CH, 1);
        mbar_wait(mb[2], 1);
        COMPUTE(bufs + 2 * CH, 2);
        mbar_wait(mb[1], 1);
        COMPUTE(bufs + 1 * CH, 3);

        // ---- two-phase pres reduction: 16 warp-partials -> 8 slots ----
        // phase 1: warps 8..15 dump their partials into pres[w16-8]
        if (w16 >= 8) {
            float* pp = pres + ((w16 - 8) * 16 + 4 * rg) * 64 + 4 * bg;
            ulonglong2 s;
            s.x = a00; s.y = a01; *(ulonglong2*)(pp + 0 * 64)      = s;
            s.x = a02; s.y = a03; *(ulonglong2*)(pp + 0 * 64 + 32) = s;
            s.x = a10; s.y = a11; *(ulonglong2*)(pp + 1 * 64)      = s;
            s.x = a12; s.y = a13; *(ulonglong2*)(pp + 1 * 64 + 32) = s;
            s.x = a20; s.y = a21; *(ulonglong2*)(pp + 2 * 64)      = s;
            s.x = a22; s.y = a23; *(ulonglong2*)(pp + 2 * 64 + 32) = s;
            s.x = a30; s.y = a31; *(ulonglong2*)(pp + 3 * 64)      = s;
            s.x = a32; s.y = a33; *(ulonglong2*)(pp + 3 * 64 + 32) = s;
        }
        __syncthreads();
        // phase 2: warps 0..7 add partner partials and write the reduced slot
        if (w16 < 8) {
            float* pp = pres + (w16 * 16 + 4 * rg) * 64 + 4 * bg;
            ulonglong2 p;
            p = *(ulonglong2*)(pp + 0 * 64);      add2(a00, p.x); add2(a01, p.y);
            p = *(ulonglong2*)(pp + 0 * 64 + 32); add2(a02, p.x); add2(a03, p.y);
            p = *(ulonglong2*)(pp + 1 * 64);      add2(a10, p.x); add2(a11, p.y);
            p = *(ulonglong2*)(pp + 1 * 64 + 32); add2(a12, p.x); add2(a13, p.y);
            p = *(ulonglong2*)(pp + 2 * 64);      add2(a20, p.x); add2(a21, p.y);
            p = *(ulonglong2*)(pp + 2 * 64 + 32); add2(a22, p.x); add2(a23, p.y);
            p = *(ulonglong2*)(pp + 3 * 64);      add2(a30, p.x); add2(a31, p.y);
            p = *(ulonglong2*)(pp + 3 * 64 + 32); add2(a32, p.x); add2(a33, p.y);
            ulonglong2 s;
            s.x = a00; s.y = a01; *(ulonglong2*)(pp + 0 * 64)      = s;
            s.x = a02; s.y = a03; *(ulonglong2*)(pp + 0 * 64 + 32) = s;
            s.x = a10; s.y = a11; *(ulonglong2*)(pp + 1 * 64)      = s;
            s.x = a12; s.y = a13; *(ulonglong2*)(pp + 1 * 64 + 32) = s;
            s.x = a20; s.y = a21; *(ulonglong2*)(pp + 2 * 64)      = s;
            s.x = a22; s.y = a23; *(ulonglong2*)(pp + 2 * 64 + 32) = s;
            s.x = a30; s.y = a31; *(ulonglong2*)(pp + 3 * 64)      = s;
            s.x = a32; s.y = a33; *(ulonglong2*)(pp + 3 * 64 + 32) = s;
        }
        __syncthreads();    // pres complete; all slots consumed

        // prefetch next step's x chunks (runs under gates + publish)
        if (tid == 0 && t + 1 < TT) {
            const float* xn = &g_xT[t + 1][0][0];
            bulk_ld(bufs + 0 * CH, xn,        mb[0]);
            bulk_ld(bufs + 1 * CH, xn + 8192, mb[1]);
        }

        // gates + state update: 256 cells, threads 0..255 (coalesced h-store)
        float* hdst = &g_hT[(t + 1) & 1][0][0];
        const int j = (tid >> 6) & 3, b = tid & 63;
        float hn = 0.0f, cn = 0.0f;
        if (tid < 256) {
            float zf = bs[j],      zi = bs[4 + j],
                  zc = bs[8 + j],  zo = bs[12 + j];
            #pragma unroll
            for (int qq = 0; qq < 8; ++qq) {
                zf += pres[(qq * 16 + 0  + j) * 64 + b];
                zi += pres[(qq * 16 + 4  + j) * 64 + b];
                zc += pres[(qq * 16 + 8  + j) * 64 + b];
                zo += pres[(qq * 16 + 12 + j) * 64 + b];
            }
            float fg = fast_sigmoid(zf);
            float ig = fast_sigmoid(zi);
            float og = fast_sigmoid(zo);
            cn = fg * cs[j * 64 + b] + ig * fast_tanh(zc);
            hn = og * fast_tanh(cn);
            cs[j * 64 + b] = cn;
            hdst[(hid0 + j) * BB + b] = hn;
        }

        // publish this CTA's arrival (h(t+1) slice visible) BEFORE out stores
        __threadfence();
        __syncthreads();
        if (tid == 0) {
            asm volatile("st.release.gpu.global.u32 [%0], %1;"
                         :: "l"(&g_flags[cta][0]), "r"((unsigned)(t + 1))
                         : "memory");
        }

        // cross-boundary prefetch of h0(t+1): poll group0 then TMA into s2
        if (t + 1 < TT) {
            poll_group(tid, 0, (unsigned)(t + 1));
            if (tid == 0) bulk_ld(bufs + 2 * CH, &g_hT[(t + 1) & 1][0][0], mb[2]);
        }

        // out stores (not on the inter-CTA critical path)
        if (tid < 256) {
            out[((size_t)t * BB + b) * HH + hid0 + j] = hn;
            if (t == TT - 1) {
                out[(size_t)TT * BB * HH + (size_t)b * HH + hid0 + j] = hn;                    // h_last
                out[(size_t)TT * BB * HH + (size_t)BB * HH + (size_t)b * HH + hid0 + j] = cn;  // c_last
            }
        }
    }
}

// ---------------- launch ----------------
extern "C" void kernel_launch(void* const* d_in, const int* in_sizes, int n_in,
                              void* d_out, int out_size) {
    const float* x  = (const float*)d_in[0];
    const float* Wf = (const float*)d_in[1];
    const float* bf = (const float*)d_in[2];
    const float* Wi = (const float*)d_in[3];
    const float* bi = (const float*)d_in[4];
    const float* Wc = (const float*)d_in[5];
    const float* bc = (const float*)d_in[6];
    const float* Wo = (const float*)d_in[7];
    const float* bo = (const float*)d_in[8];
    float* out = (float*)d_out;

    cudaFuncSetAttribute(lstm_persist,
                         cudaFuncAttributeMaxDynamicSharedMemorySize, SMEM_BYTES);

    xT_kernel<<<TT, 256>>>(x);
    lstm_persist<<<NCTA, NTHR, SMEM_BYTES>>>(Wf, bf, Wi, bi, Wc, bc, Wo, bo, out);
}